// round 16
// baseline (speedup 1.0000x reference)
#include <cuda_runtime.h>
#include <cstdint>

#define NN 100000
#define EE 800000
#define FD 128

constexpr int LDU = 68;                 // u32 per row (272B, ldmatrix conflict-free)
constexpr uint32_t ROWB = 272;
constexpr int PW = 128 * LDU;           // one 128-row plane in u32 = 34816 B
constexpr uint32_t OALO = (uint32_t)PW * 4u;   // A lo offset (bytes)
constexpr uint32_t OW   = 2u * OALO;            // W hi base (bytes)
constexpr uint32_t OWLO = (uint32_t)PW * 4u;   // W lo offset from W hi
constexpr int SMEM_BYTES = 4 * PW * 4;          // 139264

// ---------------- scratch (device globals; no allocations allowed) ----------
__device__ float g_bufA[NN * FD];
__device__ float g_bufB[NN * FD];
__device__ float g_invdeg[NN];
__device__ int   g_deg[NN];
__device__ int   g_off[NN + 1];
__device__ int   g_cnt[NN];
__device__ int   g_bsum[128];
__device__ int   g_csrc[EE];
__device__ uint32_t g_wpl[5 * 2 * PW];  // 5 weights x {hi,lo} planes, LDU layout

// ---------------- helpers ----------------------------------------------------
#define LDSM4(q, addr)                                                        \
    asm volatile("ldmatrix.sync.aligned.m8n8.x4.shared.b16 {%0,%1,%2,%3}, [%4];" \
        : "=r"((q)[0]), "=r"((q)[1]), "=r"((q)[2]), "=r"((q)[3]) : "r"(addr))

__device__ __forceinline__ uint32_t packbf(float hi, float lo) {
    uint32_t d;
    asm("cvt.rn.bf16x2.f32 %0, %1, %2;" : "=r"(d) : "f"(hi), "f"(lo));
    return d;
}

// A frags from our ldmatrix pattern: {q0,q2,q1,q3} order for mma
#define MMA_BF16(d, a, b0, b1)                                                \
    asm volatile(                                                             \
        "mma.sync.aligned.m16n8k16.row.col.f32.bf16.bf16.f32 "                \
        "{%0,%1,%2,%3}, {%4,%5,%6,%7}, {%8,%9}, {%0,%1,%2,%3};"               \
        : "+f"((d)[0]), "+f"((d)[1]), "+f"((d)[2]), "+f"((d)[3])              \
        : "r"((a)[0]), "r"((a)[2]), "r"((a)[1]), "r"((a)[3]),                 \
          "r"(b0), "r"(b1))

__device__ __forceinline__ void split4(float4 v, uint32_t& p01, uint32_t& p23,
                                       uint32_t& l01, uint32_t& l23) {
    p01 = packbf(v.y, v.x);
    p23 = packbf(v.w, v.z);
    float hx = __uint_as_float(p01 << 16), hy = __uint_as_float(p01 & 0xFFFF0000u);
    float hz = __uint_as_float(p23 << 16), hw = __uint_as_float(p23 & 0xFFFF0000u);
    l01 = packbf(v.y - hy, v.x - hx);
    l23 = packbf(v.w - hw, v.z - hz);
}

// ---------------- weight pre-split prepass -------------------------------------
__global__ void wsplit_kernel(const float* __restrict__ W1, const float* __restrict__ W2,
                              const float* __restrict__ W3, const float* __restrict__ Wo1,
                              const float* __restrict__ Wo2, uint32_t* __restrict__ planes)
{
    int w = blockIdx.x >> 3, part = blockIdx.x & 7;
    const float* W = (w == 0) ? W1 : (w == 1) ? W2 : (w == 2) ? W3 : (w == 3) ? Wo1 : Wo2;
    int rows = (w == 4) ? 64 : 128;
    int r0 = part * 16;
    if (r0 >= rows) return;
    uint32_t* Wh = planes + (size_t)w * 2 * PW;
    uint32_t* Wl = Wh + PW;
    for (int idx = threadIdx.x; idx < 16 * 32; idx += 256) {
        int r = r0 + (idx >> 5), c4 = idx & 31;
        float4 v = reinterpret_cast<const float4*>(W)[r * 32 + c4];
        uint32_t p01, p23, l01, l23;
        split4(v, p01, p23, l01, l23);
        int o = r * LDU + c4 * 2;
        Wh[o] = p01; Wh[o + 1] = p23;
        Wl[o] = l01; Wl[o + 1] = l23;
    }
}

// ---------------- bf16 3-pass mainloop, 128-row tile ---------------------------
// warp tile 64r x (NT*16)c; A frags: 4 m16 hi+lo; B frags: NT n16 hi+lo.
// acc[mi * (2*NT) + t*2 + j][4], mi 0..3
template<int NT>
__device__ __forceinline__ void mainloop_m128(
    const uint32_t* aBH, const uint32_t* bBH, float (*acc)[4])
{
    constexpr int NI = NT * 2;
    uint32_t aH[2][4][4], aL[2][4][4], bH[2][NT][4], bL[2][NT][4];
    #pragma unroll
    for (int i = 0; i < 4; ++i) { LDSM4(aH[0][i], aBH[i]); LDSM4(aL[0][i], aBH[i] + OALO); }
    #pragma unroll
    for (int t = 0; t < NT; ++t) { LDSM4(bH[0][t], bBH[t]); LDSM4(bL[0][t], bBH[t] + OWLO); }

    #pragma unroll
    for (int ks = 0; ks < 8; ++ks) {
        const int cur = ks & 1, nxt = cur ^ 1;
        if (ks < 7) {
            const uint32_t ko = (uint32_t)(ks + 1) * 32u;
            #pragma unroll
            for (int i = 0; i < 4; ++i) {
                LDSM4(aH[nxt][i], aBH[i] + ko);
                LDSM4(aL[nxt][i], aBH[i] + OALO + ko);
            }
            #pragma unroll
            for (int t = 0; t < NT; ++t) {
                LDSM4(bH[nxt][t], bBH[t] + ko);
                LDSM4(bL[nxt][t], bBH[t] + OWLO + ko);
            }
        }
        #pragma unroll
        for (int mi = 0; mi < 4; ++mi)
            #pragma unroll
            for (int t = 0; t < NT; ++t) {
                MMA_BF16(acc[mi * NI + t * 2 + 0], aH[cur][mi], bH[cur][t][0], bH[cur][t][1]);
                MMA_BF16(acc[mi * NI + t * 2 + 1], aH[cur][mi], bH[cur][t][2], bH[cur][t][3]);
            }
        #pragma unroll
        for (int mi = 0; mi < 4; ++mi)
            #pragma unroll
            for (int t = 0; t < NT; ++t) {
                MMA_BF16(acc[mi * NI + t * 2 + 0], aH[cur][mi], bL[cur][t][0], bL[cur][t][1]);
                MMA_BF16(acc[mi * NI + t * 2 + 1], aH[cur][mi], bL[cur][t][2], bL[cur][t][3]);
            }
        #pragma unroll
        for (int mi = 0; mi < 4; ++mi)
            #pragma unroll
            for (int t = 0; t < NT; ++t) {
                MMA_BF16(acc[mi * NI + t * 2 + 0], aL[cur][mi], bH[cur][t][0], bH[cur][t][1]);
                MMA_BF16(acc[mi * NI + t * 2 + 1], aL[cur][mi], bH[cur][t][2], bH[cur][t][3]);
            }
    }
}

// copy pre-split weight planes (hi+lo) from global into smem (256 threads)
template<int ROWS>
__device__ __forceinline__ void stage_wc(const uint32_t* __restrict__ Wg,
                                         uint32_t* Wh, uint32_t* Wl, int tid)
{
    const uint4* sh = reinterpret_cast<const uint4*>(Wg);
    const uint4* sl = reinterpret_cast<const uint4*>(Wg + PW);
    uint4* dh = reinterpret_cast<uint4*>(Wh);
    uint4* dl = reinterpret_cast<uint4*>(Wl);
    constexpr int NV = ROWS * (LDU / 4);   // 2176 or 1088
    #pragma unroll 4
    for (int i = tid; i < NV; i += 256) {
        dh[i] = __ldg(sh + i);
        dl[i] = __ldg(sl + i);
    }
}

// epilogue -> mid planes (128-row tile): bias + optional relu, bf16 hi/lo split
template<bool RELU>
__device__ __forceinline__ void write_mid(const float (*acc)[4], const float* bias,
                                          int wm, int wn, int qr, int qc,
                                          uint32_t* AhiU, uint32_t* AloU)
{
    const int cb = wn * 32 + qc * 2;
    #pragma unroll
    for (int ni = 0; ni < 4; ++ni) {
        int c = cb + ni * 8;
        float bb0 = __ldg(bias + c), bb1 = __ldg(bias + c + 1);
        #pragma unroll
        for (int mi = 0; mi < 4; ++mi) {
            const float* a = acc[mi * 4 + ni];
            float v0 = a[0] + bb0, v1 = a[1] + bb1, v2 = a[2] + bb0, v3 = a[3] + bb1;
            if (RELU) {
                v0 = fmaxf(v0, 0.f); v1 = fmaxf(v1, 0.f);
                v2 = fmaxf(v2, 0.f); v3 = fmaxf(v3, 0.f);
            }
            int r = wm * 64 + mi * 16 + qr;
            uint32_t p = packbf(v1, v0);
            float h0 = __uint_as_float(p << 16), h1 = __uint_as_float(p & 0xFFFF0000u);
            uint32_t l = packbf(v1 - h1, v0 - h0);
            int o = r * LDU + (c >> 1);
            AhiU[o] = p; AloU[o] = l;
            p = packbf(v3, v2);
            h0 = __uint_as_float(p << 16); h1 = __uint_as_float(p & 0xFFFF0000u);
            l = packbf(v3 - h1, v2 - h0);
            o += 8 * LDU;
            AhiU[o] = p; AloU[o] = l;
        }
    }
}

// final epilogue to global (128-row tile)
template<int NOUT, bool RELU>
__device__ __forceinline__ void write_out(const float (*acc)[4], const float* bias,
                                          float* __restrict__ out, int row0,
                                          int wm, int wn, int qr, int qc, int N)
{
    constexpr int NC = NOUT / 4;
    constexpr int NI = NC / 8;
    const int rbase = row0 + wm * 64 + qr;
    const int cbase = wn * NC + qc * 2;
    #pragma unroll
    for (int ni = 0; ni < NI; ++ni) {
        int c = cbase + ni * 8;
        float b0 = __ldg(bias + c), b1v = __ldg(bias + c + 1);
        #pragma unroll
        for (int mi = 0; mi < 4; ++mi) {
            const float* a = acc[mi * NI + ni];
            int r = rbase + mi * 16;
            float v0 = a[0] + b0, v1 = a[1] + b1v, v2 = a[2] + b0, v3 = a[3] + b1v;
            if (RELU) {
                v0 = fmaxf(v0, 0.f); v1 = fmaxf(v1, 0.f);
                v2 = fmaxf(v2, 0.f); v3 = fmaxf(v3, 0.f);
            }
            if (r < N)
                *reinterpret_cast<float2*>(out + (size_t)r * NOUT + c) = make_float2(v0, v1);
            if (r + 8 < N)
                *reinterpret_cast<float2*>(out + (size_t)(r + 8) * NOUT + c) = make_float2(v2, v3);
        }
    }
}

// ---------------- fused multi-layer GEMM, 128-row tile ------------------------
// 8 warps = 2m (64 rows each) x 4n. Weights pre-split in g_wpl; single W slot,
// staged sequentially. smem 139KB -> 1 CTA/SM, smem/tensor balanced mainloop.
template<int LAYERS, bool R2, int NOUT3, bool R3>
__global__ void __launch_bounds__(256)
gemm_fusedN(const float* __restrict__ A,
            const uint32_t* __restrict__ Wp1, const float* __restrict__ b1,
            const uint32_t* __restrict__ Wp2, const float* __restrict__ b2,
            const uint32_t* __restrict__ Wp3, const float* __restrict__ b3,
            float* __restrict__ out, int N)
{
    extern __shared__ uint16_t smh[];
    uint32_t* U    = reinterpret_cast<uint32_t*>(smh);
    uint32_t* AhiU = U;                 // [128][LDU]
    uint32_t* AloU = U + PW;
    uint32_t* Wh   = U + 2 * PW;        // [128][LDU] (current weight)
    uint32_t* Wl   = Wh + PW;

    const int tid  = threadIdx.x;
    const int wid  = tid >> 5;
    const int lane = tid & 31;
    const int wm   = wid & 1;           // 2 m-warps x 64 rows
    const int wn   = wid >> 1;          // 4 n-warps
    const int row0 = blockIdx.x * 128;
    const int qr   = lane >> 2;
    const int qc   = lane & 3;

    // ---- stage A (128 rows) ----
    #pragma unroll
    for (int it = 0; it < 16; ++it) {
        int idx = tid + it * 256;
        int r = idx >> 5, c4 = idx & 31;
        int row = row0 + r;
        float4 v = make_float4(0.f, 0.f, 0.f, 0.f);
        if (row < N) v = reinterpret_cast<const float4*>(A)[(size_t)row * 32 + c4];
        uint32_t p01, p23, l01, l23;
        split4(v, p01, p23, l01, l23);
        int o = r * LDU + c4 * 2;
        AhiU[o] = p01; AhiU[o + 1] = p23;
        AloU[o] = l01; AloU[o + 1] = l23;
    }
    stage_wc<128>(Wp1, Wh, Wl, tid);
    __syncthreads();

    uint32_t sb;
    asm("{ .reg .u64 t; cvta.to.shared.u64 t, %1; cvt.u32.u64 %0, t; }" : "=r"(sb) : "l"(smh));
    const int m  = lane >> 3;
    const int mr = ((m >> 1) << 3) + (lane & 7);
    const uint32_t mc = (uint32_t)(m & 1) * 16u;

    uint32_t aBH[4];
    #pragma unroll
    for (int i = 0; i < 4; ++i)
        aBH[i] = sb + (uint32_t)(wm * 64 + i * 16 + mr) * ROWB + mc;
    uint32_t bBH2[2];
    #pragma unroll
    for (int t = 0; t < 2; ++t)
        bBH2[t] = sb + OW + (uint32_t)(wn * 32 + t * 16 + mr) * ROWB + mc;

    // ---- GEMM1 (W1, relu -> mid) ----
    {
        float acc[16][4];
        #pragma unroll
        for (int i = 0; i < 16; ++i)
            #pragma unroll
            for (int c = 0; c < 4; ++c) acc[i][c] = 0.f;
        mainloop_m128<2>(aBH, bBH2, acc);
        __syncthreads();                       // A + W1 reads done
        write_mid<true>(acc, b1, wm, wn, qr, qc, AhiU, AloU);
        stage_wc<128>(Wp2, Wh, Wl, tid);       // restage W2 over W1
    }
    __syncthreads();

    if (LAYERS == 2) {
        float acc[16][4];
        #pragma unroll
        for (int i = 0; i < 16; ++i)
            #pragma unroll
            for (int c = 0; c < 4; ++c) acc[i][c] = 0.f;
        mainloop_m128<2>(aBH, bBH2, acc);
        write_out<128, false>(acc, b2, out, row0, wm, wn, qr, qc, N);
        return;
    }

    // ---- GEMM2 (W2, R2 -> mid) ----
    {
        float acc[16][4];
        #pragma unroll
        for (int i = 0; i < 16; ++i)
            #pragma unroll
            for (int c = 0; c < 4; ++c) acc[i][c] = 0.f;
        mainloop_m128<2>(aBH, bBH2, acc);
        __syncthreads();                       // mid1 + W2 reads done
        write_mid<R2>(acc, b2, wm, wn, qr, qc, AhiU, AloU);
        stage_wc<NOUT3>(Wp3, Wh, Wl, tid);     // restage W3 over W2
    }
    __syncthreads();

    // ---- GEMM3 final (W3, NOUT3, R3) ----
    constexpr int NT3 = (NOUT3 / 4) / 16;      // 2 or 1
    constexpr int NI3 = NT3 * 2;
    float acc3[4 * NI3][4];
    #pragma unroll
    for (int i = 0; i < 4 * NI3; ++i)
        #pragma unroll
        for (int c = 0; c < 4; ++c) acc3[i][c] = 0.f;
    uint32_t bBH3[NT3];
    #pragma unroll
    for (int t = 0; t < NT3; ++t)
        bBH3[t] = sb + OW + (uint32_t)(wn * (NOUT3 / 4) + t * 16 + mr) * ROWB + mc;
    mainloop_m128<NT3>(aBH, bBH3, acc3);
    write_out<NOUT3, R3>(acc3, b3, out, row0, wm, wn, qr, qc, N);
}

// ---------------- CSR build ---------------------------------------------------
__global__ void zero_int_kernel(int* p, int n) {
    int i = blockIdx.x * blockDim.x + threadIdx.x;
    if (i < n) p[i] = 0;
}
__global__ void hist_kernel(const int* __restrict__ dst, int E, int* __restrict__ deg) {
    int i = blockIdx.x * blockDim.x + threadIdx.x;
    if (i < E) atomicAdd(&deg[dst[i]], 1);
}
__global__ void csr_scan1(const int* __restrict__ deg, int* __restrict__ off,
                          int* __restrict__ bsum, float* __restrict__ invd,
                          int* __restrict__ cnt, int n) {
    __shared__ int s[1024];
    int g = blockIdx.x * 1024 + threadIdx.x;
    int v = (g < n) ? deg[g] : 0;
    if (g < n) { invd[g] = 1.0f / fmaxf((float)v, 1.0f); cnt[g] = 0; }
    s[threadIdx.x] = v;
    __syncthreads();
    #pragma unroll
    for (int d = 1; d < 1024; d <<= 1) {
        int t = (threadIdx.x >= d) ? s[threadIdx.x - d] : 0;
        __syncthreads();
        s[threadIdx.x] += t;
        __syncthreads();
    }
    if (g < n) off[g + 1] = s[threadIdx.x];
    if (threadIdx.x == 1023) bsum[blockIdx.x] = s[1023];
}
__global__ void csr_scan2(int* bsum, int nb) {
    __shared__ int s[128];
    int v = (threadIdx.x < nb) ? bsum[threadIdx.x] : 0;
    s[threadIdx.x] = v;
    __syncthreads();
    #pragma unroll
    for (int d = 1; d < 128; d <<= 1) {
        int t = (threadIdx.x >= d) ? s[threadIdx.x - d] : 0;
        __syncthreads();
        s[threadIdx.x] += t;
        __syncthreads();
    }
    if (threadIdx.x < nb) bsum[threadIdx.x] = s[threadIdx.x] - v;  // exclusive
}
__global__ void csr_scan3(int* __restrict__ off, const int* __restrict__ bsum, int n) {
    int g = blockIdx.x * 1024 + threadIdx.x;
    if (g < n) off[g + 1] += bsum[blockIdx.x];
    if (g == 0) off[0] = 0;
}
__global__ void csr_fill(const int* __restrict__ src, const int* __restrict__ dst,
                         const int* __restrict__ off, int* __restrict__ cnt,
                         int* __restrict__ csrc, int E) {
    int i = blockIdx.x * blockDim.x + threadIdx.x;
    if (i < E) {
        int d = dst[i];
        int p = off[d] + atomicAdd(&cnt[d], 1);
        csrc[p] = src[i];
    }
}

// ---------------- fused mean-aggregate: out = h + mean_in(h) ------------------
__global__ void aggregate_kernel(const float* __restrict__ h, const int* __restrict__ off,
                                 const int* __restrict__ csrc, const float* __restrict__ invd,
                                 float* __restrict__ out, int N)
{
    int wid  = threadIdx.x >> 5;
    int lane = threadIdx.x & 31;
    int node = blockIdx.x * (blockDim.x >> 5) + wid;
    if (node >= N) return;
    int beg = off[node], end = off[node + 1];
    float4 acc = make_float4(0.f, 0.f, 0.f, 0.f);
    const float4* h4 = reinterpret_cast<const float4*>(h);
    int e = beg;
    for (; e + 7 < end; e += 8) {
        int s[8];
        #pragma unroll
        for (int j = 0; j < 8; ++j) s[j] = __ldg(csrc + e + j);
        float4 v[8];
        #pragma unroll
        for (int j = 0; j < 8; ++j) v[j] = __ldg(h4 + s[j] * 32 + lane);
        #pragma unroll
        for (int j = 0; j < 8; ++j) {
            acc.x += v[j].x; acc.y += v[j].y; acc.z += v[j].z; acc.w += v[j].w;
        }
    }
    for (; e + 3 < end; e += 4) {
        int s0 = __ldg(csrc + e),     s1 = __ldg(csrc + e + 1);
        int s2 = __ldg(csrc + e + 2), s3 = __ldg(csrc + e + 3);
        float4 v0 = __ldg(h4 + s0 * 32 + lane);
        float4 v1 = __ldg(h4 + s1 * 32 + lane);
        float4 v2 = __ldg(h4 + s2 * 32 + lane);
        float4 v3 = __ldg(h4 + s3 * 32 + lane);
        acc.x += (v0.x + v1.x) + (v2.x + v3.x);
        acc.y += (v0.y + v1.y) + (v2.y + v3.y);
        acc.z += (v0.z + v1.z) + (v2.z + v3.z);
        acc.w += (v0.w + v1.w) + (v2.w + v3.w);
    }
    for (; e < end; ++e) {
        int s0 = __ldg(csrc + e);
        float4 v0 = __ldg(h4 + s0 * 32 + lane);
        acc.x += v0.x; acc.y += v0.y; acc.z += v0.z; acc.w += v0.w;
    }
    float iv = invd[node];
    float4 b = __ldg(h4 + node * 32 + lane);
    reinterpret_cast<float4*>(out)[node * 32 + lane] =
        make_float4(b.x + acc.x * iv, b.y + acc.y * iv,
                    b.z + acc.z * iv, b.w + acc.w * iv);
}

// ---------------- launch -----------------------------------------------------
extern "C" void kernel_launch(void* const* d_in, const int* in_sizes, int n_in,
                              void* d_out, int out_size)
{
    const float* x   = (const float*)d_in[0];
    const int*   src = (const int*)  d_in[1];
    const int*   dst = (const int*)  d_in[2];
    const float* W1  = (const float*)d_in[3];
    const float* b1  = (const float*)d_in[4];
    const float* W2  = (const float*)d_in[5];
    const float* b2  = (const float*)d_in[6];
    const float* W3  = (const float*)d_in[7];
    const float* b3  = (const float*)d_in[8];
    const float* Wo1 = (const float*)d_in[9];
    const float* bo1 = (const float*)d_in[10];
    const float* Wo2 = (const float*)d_in[11];
    const float* bo2 = (const float*)d_in[12];
    float* out = (float*)d_out;

    const int N = in_sizes[0] / FD;    // 100000
    const int E = in_sizes[1];         // 800000

    float *bufA, *bufB, *invd;
    int *deg, *off, *cnt, *bsum, *csrc;
    uint32_t* wpl;
    cudaGetSymbolAddress((void**)&bufA, g_bufA);
    cudaGetSymbolAddress((void**)&bufB, g_bufB);
    cudaGetSymbolAddress((void**)&invd, g_invdeg);
    cudaGetSymbolAddress((void**)&deg,  g_deg);
    cudaGetSymbolAddress((void**)&off,  g_off);
    cudaGetSymbolAddress((void**)&cnt,  g_cnt);
    cudaGetSymbolAddress((void**)&bsum, g_bsum);
    cudaGetSymbolAddress((void**)&csrc, g_csrc);
    cudaGetSymbolAddress((void**)&wpl,  g_wpl);

    // side stream + fork/join events (created once; capture-safe)
    static cudaStream_t sCSR = nullptr;
    static cudaEvent_t  evFork = nullptr, evJoin = nullptr;
    if (!sCSR) {
        cudaStreamCreateWithFlags(&sCSR, cudaStreamNonBlocking);
        cudaEventCreateWithFlags(&evFork, cudaEventDisableTiming);
        cudaEventCreateWithFlags(&evJoin, cudaEventDisableTiming);
    }

    cudaFuncSetAttribute(gemm_fusedN<2, false, 128, false>, cudaFuncAttributeMaxDynamicSharedMemorySize, SMEM_BYTES);
    cudaFuncSetAttribute(gemm_fusedN<3, false, 128, true >, cudaFuncAttributeMaxDynamicSharedMemorySize, SMEM_BYTES);
    cudaFuncSetAttribute(gemm_fusedN<3, true,  64,  false>, cudaFuncAttributeMaxDynamicSharedMemorySize, SMEM_BYTES);

    const int gb = (N + 127) / 128;               // 782 (128-row tiles)
    const int nb = (N + 1023) / 1024;             // 98 scan blocks
    const int ag = (N + 7) / 8;                   // aggregate: 8 warps/block

    const uint32_t* p0 = wpl;                     // W1
    const uint32_t* p1 = wpl + 1 * 2 * PW;        // W2
    const uint32_t* p2 = wpl + 2 * 2 * PW;        // W3
    const uint32_t* p3 = wpl + 3 * 2 * PW;        // Wo1
    const uint32_t* p4 = wpl + 4 * 2 * PW;        // Wo2

    // ---- fork: CSR build on side stream ----
    cudaEventRecord(evFork, 0);
    cudaStreamWaitEvent(sCSR, evFork, 0);

    zero_int_kernel<<<(N + 255) / 256, 256, 0, sCSR>>>(deg, N);
    hist_kernel<<<(E + 255) / 256, 256, 0, sCSR>>>(dst, E, deg);
    csr_scan1<<<nb, 1024, 0, sCSR>>>(deg, off, bsum, invd, cnt, N);
    csr_scan2<<<1, 128, 0, sCSR>>>(bsum, nb);
    csr_scan3<<<nb, 1024, 0, sCSR>>>(off, bsum, N);
    csr_fill<<<(E + 255) / 256, 256, 0, sCSR>>>(src, dst, off, cnt, csrc, E);
    cudaEventRecord(evJoin, sCSR);

    // ---- weight pre-split (once per call; tiny) ----
    wsplit_kernel<<<40, 256>>>(W1, W2, W3, Wo1, Wo2, wpl);

    // x2 = lin(relu(lin(x,W1,b1)),W2,b2)
    gemm_fusedN<2, false, 128, false><<<gb, 256, SMEM_BYTES>>>(
        x, p0, b1, p1, b2, nullptr, nullptr, bufA, N);

    // ---- join before first aggregate ----
    cudaStreamWaitEvent(0, evJoin, 0);

    // h = x2 + mean_agg(x2)
    aggregate_kernel<<<ag, 256>>>(bufA, off, csrc, invd, bufB, N);

    // h = relu(lin( lin(relu(lin(h,W1,b1)),W2,b2), W3,b3))
    gemm_fusedN<3, false, 128, true><<<gb, 256, SMEM_BYTES>>>(
        bufB, p0, b1, p1, b2, p2, b3, bufA, N);

    // h = h + mean_agg(h)
    aggregate_kernel<<<ag, 256>>>(bufA, off, csrc, invd, bufB, N);

    // out = lin( relu(lin( relu(lin(h,W3,b3)), Wo1,bo1)), Wo2,bo2)
    gemm_fusedN<3, true, 64, false><<<gb, 256, SMEM_BYTES>>>(
        bufB, p2, b3, p3, bo1, p4, bo2, out, N);
}

// round 17
// speedup vs baseline: 1.2590x; 1.2590x over previous
#include <cuda_runtime.h>
#include <cstdint>

#define NN 100000
#define EE 800000
#define FD 128

constexpr int LDU = 68;                 // u32 per row (272B, ldmatrix conflict-free)
constexpr uint32_t ROWB = 272;
constexpr int PA = 64 * LDU;            // A plane (64 rows) in u32    = 17408 B
constexpr int PW = 128 * LDU;           // W plane (128 rows) in u32   = 34816 B
constexpr uint32_t OALO = (uint32_t)PA * 4u;      // A lo offset (bytes)
constexpr uint32_t OW   = 2u * OALO;               // W hi base (bytes)
constexpr uint32_t OWLO = (uint32_t)PW * 4u;      // W lo offset from W hi
constexpr int SMEM_BYTES = 2 * (PA + PW) * 4;      // 104448

// ---------------- scratch (device globals; no allocations allowed) ----------
__device__ float g_bufA[NN * FD];
__device__ float g_bufB[NN * FD];
__device__ float g_invdeg[NN];
__device__ int   g_deg[NN];
__device__ int   g_off[NN + 1];
__device__ int   g_cnt[NN];
__device__ int   g_bsum[128];
__device__ int   g_csrc[EE];
__device__ uint32_t g_wpl[5 * 2 * PW];  // 5 weights x {hi,lo} planes, LDU layout

// ---------------- helpers ----------------------------------------------------
#define LDSM4(q, addr)                                                        \
    asm volatile("ldmatrix.sync.aligned.m8n8.x4.shared.b16 {%0,%1,%2,%3}, [%4];" \
        : "=r"((q)[0]), "=r"((q)[1]), "=r"((q)[2]), "=r"((q)[3]) : "r"(addr))

__device__ __forceinline__ uint32_t packbf(float hi, float lo) {
    uint32_t d;
    asm("cvt.rn.bf16x2.f32 %0, %1, %2;" : "=r"(d) : "f"(hi), "f"(lo));
    return d;
}

// A frags from our ldmatrix pattern: {q0,q2,q1,q3} order for mma
#define MMA_BF16(d, a, b0, b1)                                                \
    asm volatile(                                                             \
        "mma.sync.aligned.m16n8k16.row.col.f32.bf16.bf16.f32 "                \
        "{%0,%1,%2,%3}, {%4,%5,%6,%7}, {%8,%9}, {%0,%1,%2,%3};"               \
        : "+f"((d)[0]), "+f"((d)[1]), "+f"((d)[2]), "+f"((d)[3])              \
        : "r"((a)[0]), "r"((a)[2]), "r"((a)[1]), "r"((a)[3]),                 \
          "r"(b0), "r"(b1))

__device__ __forceinline__ void split4(float4 v, uint32_t& p01, uint32_t& p23,
                                       uint32_t& l01, uint32_t& l23) {
    p01 = packbf(v.y, v.x);
    p23 = packbf(v.w, v.z);
    float hx = __uint_as_float(p01 << 16), hy = __uint_as_float(p01 & 0xFFFF0000u);
    float hz = __uint_as_float(p23 << 16), hw = __uint_as_float(p23 & 0xFFFF0000u);
    l01 = packbf(v.y - hy, v.x - hx);
    l23 = packbf(v.w - hw, v.z - hz);
}

// 16B async copy global->shared (Ampere+ LDGSTS)
__device__ __forceinline__ void cp16(uint32_t saddr, const void* gaddr) {
    asm volatile("cp.async.cg.shared.global [%0], [%1], 16;"
                 :: "r"(saddr), "l"(gaddr) : "memory");
}
__device__ __forceinline__ void cp_commit() {
    asm volatile("cp.async.commit_group;" ::: "memory");
}
__device__ __forceinline__ void cp_wait0() {
    asm volatile("cp.async.wait_group 0;" ::: "memory");
}

// ---------------- weight pre-split prepass -------------------------------------
__global__ void wsplit_kernel(const float* __restrict__ W1, const float* __restrict__ W2,
                              const float* __restrict__ W3, const float* __restrict__ Wo1,
                              const float* __restrict__ Wo2, uint32_t* __restrict__ planes)
{
    int w = blockIdx.x >> 3, part = blockIdx.x & 7;
    const float* W = (w == 0) ? W1 : (w == 1) ? W2 : (w == 2) ? W3 : (w == 3) ? Wo1 : Wo2;
    int rows = (w == 4) ? 64 : 128;
    int r0 = part * 16;
    if (r0 >= rows) return;
    uint32_t* Wh = planes + (size_t)w * 2 * PW;
    uint32_t* Wl = Wh + PW;
    for (int idx = threadIdx.x; idx < 16 * 32; idx += 256) {
        int r = r0 + (idx >> 5), c4 = idx & 31;
        float4 v = reinterpret_cast<const float4*>(W)[r * 32 + c4];
        uint32_t p01, p23, l01, l23;
        split4(v, p01, p23, l01, l23);
        int o = r * LDU + c4 * 2;
        Wh[o] = p01; Wh[o + 1] = p23;
        Wl[o] = l01; Wl[o + 1] = l23;
    }
}

// ---------------- shared bf16 3-pass mainloop (K=128, 8 k16 steps) -----------
template<int NT>
__device__ __forceinline__ void bf16_mainloop(
    uint32_t aBH0, uint32_t aBH1, uint32_t aBL0, uint32_t aBL1,
    const uint32_t* bBH, const uint32_t* bBL, float (*acc)[4])
{
    constexpr int NI = NT * 2;
    uint32_t aH[2][2][4], aL[2][2][4], bH[2][NT][4], bL[2][NT][4];
    LDSM4(aH[0][0], aBH0); LDSM4(aH[0][1], aBH1);
    LDSM4(aL[0][0], aBL0); LDSM4(aL[0][1], aBL1);
    #pragma unroll
    for (int t = 0; t < NT; ++t) { LDSM4(bH[0][t], bBH[t]); LDSM4(bL[0][t], bBL[t]); }

    #pragma unroll
    for (int ks = 0; ks < 8; ++ks) {
        const int cur = ks & 1, nxt = cur ^ 1;
        if (ks < 7) {
            const uint32_t ko = (uint32_t)(ks + 1) * 32u;
            LDSM4(aH[nxt][0], aBH0 + ko); LDSM4(aH[nxt][1], aBH1 + ko);
            LDSM4(aL[nxt][0], aBL0 + ko); LDSM4(aL[nxt][1], aBL1 + ko);
            #pragma unroll
            for (int t = 0; t < NT; ++t) {
                LDSM4(bH[nxt][t], bBH[t] + ko);
                LDSM4(bL[nxt][t], bBL[t] + ko);
            }
        }
        #pragma unroll
        for (int mi = 0; mi < 2; ++mi)
            #pragma unroll
            for (int t = 0; t < NT; ++t) {
                MMA_BF16(acc[mi * NI + t * 2 + 0], aH[cur][mi], bH[cur][t][0], bH[cur][t][1]);
                MMA_BF16(acc[mi * NI + t * 2 + 1], aH[cur][mi], bH[cur][t][2], bH[cur][t][3]);
            }
        #pragma unroll
        for (int mi = 0; mi < 2; ++mi)
            #pragma unroll
            for (int t = 0; t < NT; ++t) {
                MMA_BF16(acc[mi * NI + t * 2 + 0], aH[cur][mi], bL[cur][t][0], bL[cur][t][1]);
                MMA_BF16(acc[mi * NI + t * 2 + 1], aH[cur][mi], bL[cur][t][2], bL[cur][t][3]);
            }
        #pragma unroll
        for (int mi = 0; mi < 2; ++mi)
            #pragma unroll
            for (int t = 0; t < NT; ++t) {
                MMA_BF16(acc[mi * NI + t * 2 + 0], aL[cur][mi], bH[cur][t][0], bH[cur][t][1]);
                MMA_BF16(acc[mi * NI + t * 2 + 1], aL[cur][mi], bH[cur][t][2], bH[cur][t][3]);
            }
    }
}

// async-copy pre-split weight planes (hi+lo) global->smem; caller commits/waits
template<int ROWS>
__device__ __forceinline__ void stage_wc_async(const uint32_t* __restrict__ Wg,
                                               uint32_t sWh, int tid)
{
    constexpr int NV = ROWS * (LDU / 4);   // uint4 count: 2176 or 1088
    const uint4* sh = reinterpret_cast<const uint4*>(Wg);
    const uint4* sl = reinterpret_cast<const uint4*>(Wg + PW);
    #pragma unroll 4
    for (int i = tid; i < NV; i += 256) {
        cp16(sWh + (uint32_t)i * 16u, sh + i);
        cp16(sWh + OWLO + (uint32_t)i * 16u, sl + i);
    }
    cp_commit();
}

// epilogue -> mid planes (64-row tile): bias + optional relu, bf16 hi/lo split
template<bool RELU>
__device__ __forceinline__ void write_mid(const float (*acc)[4], const float* bias,
                                          int wm, int wn, int qr, int qc,
                                          uint32_t* AhiU, uint32_t* AloU)
{
    const int cb = wn * 32 + qc * 2;
    #pragma unroll
    for (int ni = 0; ni < 4; ++ni) {
        int c = cb + ni * 8;
        float bb0 = __ldg(bias + c), bb1 = __ldg(bias + c + 1);
        #pragma unroll
        for (int mi = 0; mi < 2; ++mi) {
            const float* a = acc[mi * 4 + ni];
            float v0 = a[0] + bb0, v1 = a[1] + bb1, v2 = a[2] + bb0, v3 = a[3] + bb1;
            if (RELU) {
                v0 = fmaxf(v0, 0.f); v1 = fmaxf(v1, 0.f);
                v2 = fmaxf(v2, 0.f); v3 = fmaxf(v3, 0.f);
            }
            int r = wm * 32 + mi * 16 + qr;
            uint32_t p = packbf(v1, v0);
            float h0 = __uint_as_float(p << 16), h1 = __uint_as_float(p & 0xFFFF0000u);
            uint32_t l = packbf(v1 - h1, v0 - h0);
            int o = r * LDU + (c >> 1);
            AhiU[o] = p; AloU[o] = l;
            p = packbf(v3, v2);
            h0 = __uint_as_float(p << 16); h1 = __uint_as_float(p & 0xFFFF0000u);
            l = packbf(v3 - h1, v2 - h0);
            o += 8 * LDU;
            AhiU[o] = p; AloU[o] = l;
        }
    }
}

// final epilogue to global
template<int NOUT, bool RELU>
__device__ __forceinline__ void write_out(const float (*acc)[4], const float* bias,
                                          float* __restrict__ out, int row0,
                                          int wm, int wn, int qr, int qc, int N)
{
    constexpr int NC = NOUT / 4;
    constexpr int NI = NC / 8;
    const int rbase = row0 + wm * 32 + qr;
    const int cbase = wn * NC + qc * 2;
    #pragma unroll
    for (int ni = 0; ni < NI; ++ni) {
        int c = cbase + ni * 8;
        float b0 = __ldg(bias + c), b1v = __ldg(bias + c + 1);
        #pragma unroll
        for (int mi = 0; mi < 2; ++mi) {
            const float* a = acc[mi * NI + ni];
            int r = rbase + mi * 16;
            float v0 = a[0] + b0, v1 = a[1] + b1v, v2 = a[2] + b0, v3 = a[3] + b1v;
            if (RELU) {
                v0 = fmaxf(v0, 0.f); v1 = fmaxf(v1, 0.f);
                v2 = fmaxf(v2, 0.f); v3 = fmaxf(v3, 0.f);
            }
            if (r < N)
                *reinterpret_cast<float2*>(out + (size_t)r * NOUT + c) = make_float2(v0, v1);
            if (r + 8 < N)
                *reinterpret_cast<float2*>(out + (size_t)(r + 8) * NOUT + c) = make_float2(v2, v3);
        }
    }
}

// ---------------- fused multi-layer GEMM, 64-row tile, 2 CTAs/SM ---------------
// Weights come pre-split from g_wpl; restaged via cp.async overlapped with
// the mid-plane epilogue.
template<int LAYERS, bool R2, int NOUT3, bool R3>
__global__ void __launch_bounds__(256, 2)
gemm_fusedN(const float* __restrict__ A,
            const uint32_t* __restrict__ Wp1, const float* __restrict__ b1,
            const uint32_t* __restrict__ Wp2, const float* __restrict__ b2,
            const uint32_t* __restrict__ Wp3, const float* __restrict__ b3,
            float* __restrict__ out, int N)
{
    extern __shared__ uint16_t smh[];
    uint32_t* U    = reinterpret_cast<uint32_t*>(smh);
    uint32_t* AhiU = U;                 // [64][LDU]
    uint32_t* AloU = U + PA;

    const int tid  = threadIdx.x;
    const int wid  = tid >> 5;
    const int lane = tid & 31;
    const int wm   = wid & 1;           // 2 m-warps x 32 rows
    const int wn   = wid >> 1;          // 4 n-warps
    const int row0 = blockIdx.x * 64;
    const int qr   = lane >> 2;
    const int qc   = lane & 3;

    uint32_t sb;
    asm("{ .reg .u64 t; cvta.to.shared.u64 t, %1; cvt.u32.u64 %0, t; }" : "=r"(sb) : "l"(smh));
    const uint32_t sW = sb + OW;

    // ---- kick off W1 async copy, then stage A (overlap) ----
    stage_wc_async<128>(Wp1, sW, tid);
    #pragma unroll
    for (int it = 0; it < 8; ++it) {
        int idx = tid + it * 256;
        int r = idx >> 5, c4 = idx & 31;
        int row = row0 + r;
        float4 v = make_float4(0.f, 0.f, 0.f, 0.f);
        if (row < N) v = reinterpret_cast<const float4*>(A)[(size_t)row * 32 + c4];
        uint32_t p01, p23, l01, l23;
        split4(v, p01, p23, l01, l23);
        int o = r * LDU + c4 * 2;
        AhiU[o] = p01; AhiU[o + 1] = p23;
        AloU[o] = l01; AloU[o + 1] = l23;
    }
    cp_wait0();
    __syncthreads();

    const int m  = lane >> 3;
    const int mr = ((m >> 1) << 3) + (lane & 7);
    const uint32_t mc = (uint32_t)(m & 1) * 16u;
    const uint32_t aBH0 = sb + (uint32_t)(wm * 32 + 0  + mr) * ROWB + mc;
    const uint32_t aBH1 = sb + (uint32_t)(wm * 32 + 16 + mr) * ROWB + mc;

    uint32_t bB[2], bL[2];
    #pragma unroll
    for (int t = 0; t < 2; ++t) {
        bB[t] = sW + (uint32_t)(wn * 32 + t * 16 + mr) * ROWB + mc;
        bL[t] = bB[t] + OWLO;
    }

    // ---- GEMM1 (W1, relu -> mid) ----
    {
        float acc[8][4];
        #pragma unroll
        for (int i = 0; i < 8; ++i)
            #pragma unroll
            for (int c = 0; c < 4; ++c) acc[i][c] = 0.f;
        bf16_mainloop<2>(aBH0, aBH1, aBH0 + OALO, aBH1 + OALO, bB, bL, acc);
        __syncthreads();                       // A + W1 reads done
        stage_wc_async<128>(Wp2, sW, tid);     // W2 copy flies under write_mid
        write_mid<true>(acc, b1, wm, wn, qr, qc, AhiU, AloU);
        cp_wait0();
    }
    __syncthreads();

    if (LAYERS == 2) {
        // ---- GEMM2 final (W2, NOUT=128, no relu) ----
        float acc[8][4];
        #pragma unroll
        for (int i = 0; i < 8; ++i)
            #pragma unroll
            for (int c = 0; c < 4; ++c) acc[i][c] = 0.f;
        bf16_mainloop<2>(aBH0, aBH1, aBH0 + OALO, aBH1 + OALO, bB, bL, acc);
        write_out<128, false>(acc, b2, out, row0, wm, wn, qr, qc, N);
        return;
    }

    // ---- GEMM2 (W2, R2 -> mid) ----
    {
        float acc[8][4];
        #pragma unroll
        for (int i = 0; i < 8; ++i)
            #pragma unroll
            for (int c = 0; c < 4; ++c) acc[i][c] = 0.f;
        bf16_mainloop<2>(aBH0, aBH1, aBH0 + OALO, aBH1 + OALO, bB, bL, acc);
        __syncthreads();                       // mid1 + W2 reads done
        stage_wc_async<NOUT3>(Wp3, sW, tid);   // W3 copy flies under write_mid
        write_mid<R2>(acc, b2, wm, wn, qr, qc, AhiU, AloU);
        cp_wait0();
    }
    __syncthreads();

    // ---- GEMM3 final (W3, NOUT3, R3) ----
    constexpr int NT3 = (NOUT3 / 4) / 16;      // 2 or 1
    constexpr int NI3 = NT3 * 2;
    float acc3[2 * NI3][4];
    #pragma unroll
    for (int i = 0; i < 2 * NI3; ++i)
        #pragma unroll
        for (int c = 0; c < 4; ++c) acc3[i][c] = 0.f;
    uint32_t bB3[NT3], bL3[NT3];
    #pragma unroll
    for (int t = 0; t < NT3; ++t) {
        bB3[t] = sW + (uint32_t)(wn * (NOUT3 / 4) + t * 16 + mr) * ROWB + mc;
        bL3[t] = bB3[t] + OWLO;
    }
    bf16_mainloop<NT3>(aBH0, aBH1, aBH0 + OALO, aBH1 + OALO, bB3, bL3, acc3);
    write_out<NOUT3, R3>(acc3, b3, out, row0, wm, wn, qr, qc, N);
}

// ---------------- CSR build ---------------------------------------------------
__global__ void zero_int_kernel(int* p, int n) {
    int i = blockIdx.x * blockDim.x + threadIdx.x;
    if (i < n) p[i] = 0;
}
__global__ void hist_kernel(const int* __restrict__ dst, int E, int* __restrict__ deg) {
    int i = blockIdx.x * blockDim.x + threadIdx.x;
    if (i < E) atomicAdd(&deg[dst[i]], 1);
}
__global__ void csr_scan1(const int* __restrict__ deg, int* __restrict__ off,
                          int* __restrict__ bsum, float* __restrict__ invd,
                          int* __restrict__ cnt, int n) {
    __shared__ int s[1024];
    int g = blockIdx.x * 1024 + threadIdx.x;
    int v = (g < n) ? deg[g] : 0;
    if (g < n) { invd[g] = 1.0f / fmaxf((float)v, 1.0f); cnt[g] = 0; }
    s[threadIdx.x] = v;
    __syncthreads();
    #pragma unroll
    for (int d = 1; d < 1024; d <<= 1) {
        int t = (threadIdx.x >= d) ? s[threadIdx.x - d] : 0;
        __syncthreads();
        s[threadIdx.x] += t;
        __syncthreads();
    }
    if (g < n) off[g + 1] = s[threadIdx.x];
    if (threadIdx.x == 1023) bsum[blockIdx.x] = s[1023];
}
__global__ void csr_scan2(int* bsum, int nb) {
    __shared__ int s[128];
    int v = (threadIdx.x < nb) ? bsum[threadIdx.x] : 0;
    s[threadIdx.x] = v;
    __syncthreads();
    #pragma unroll
    for (int d = 1; d < 128; d <<= 1) {
        int t = (threadIdx.x >= d) ? s[threadIdx.x - d] : 0;
        __syncthreads();
        s[threadIdx.x] += t;
        __syncthreads();
    }
    if (threadIdx.x < nb) bsum[threadIdx.x] = s[threadIdx.x] - v;  // exclusive
}
__global__ void csr_scan3(int* __restrict__ off, const int* __restrict__ bsum, int n) {
    int g = blockIdx.x * 1024 + threadIdx.x;
    if (g < n) off[g + 1] += bsum[blockIdx.x];
    if (g == 0) off[0] = 0;
}
__global__ void csr_fill(const int* __restrict__ src, const int* __restrict__ dst,
                         const int* __restrict__ off, int* __restrict__ cnt,
                         int* __restrict__ csrc, int E) {
    int i = blockIdx.x * blockDim.x + threadIdx.x;
    if (i < E) {
        int d = dst[i];
        int p = off[d] + atomicAdd(&cnt[d], 1);
        csrc[p] = src[i];
    }
}

// ---------------- fused mean-aggregate: out = h + mean_in(h) ------------------
__global__ void aggregate_kernel(const float* __restrict__ h, const int* __restrict__ off,
                                 const int* __restrict__ csrc, const float* __restrict__ invd,
                                 float* __restrict__ out, int N)
{
    int wid  = threadIdx.x >> 5;
    int lane = threadIdx.x & 31;
    int node = blockIdx.x * (blockDim.x >> 5) + wid;
    if (node >= N) return;
    int beg = off[node], end = off[node + 1];
    float4 acc = make_float4(0.f, 0.f, 0.f, 0.f);
    const float4* h4 = reinterpret_cast<const float4*>(h);
    int e = beg;
    for (; e + 7 < end; e += 8) {
        int s[8];
        #pragma unroll
        for (int j = 0; j < 8; ++j) s[j] = __ldg(csrc + e + j);
        float4 v[8];
        #pragma unroll
        for (int j = 0; j < 8; ++j) v[j] = __ldg(h4 + s[j] * 32 + lane);
        #pragma unroll
        for (int j = 0; j < 8; ++j) {
            acc.x += v[j].x; acc.y += v[j].y; acc.z += v[j].z; acc.w += v[j].w;
        }
    }
    for (; e + 3 < end; e += 4) {
        int s0 = __ldg(csrc + e),     s1 = __ldg(csrc + e + 1);
        int s2 = __ldg(csrc + e + 2), s3 = __ldg(csrc + e + 3);
        float4 v0 = __ldg(h4 + s0 * 32 + lane);
        float4 v1 = __ldg(h4 + s1 * 32 + lane);
        float4 v2 = __ldg(h4 + s2 * 32 + lane);
        float4 v3 = __ldg(h4 + s3 * 32 + lane);
        acc.x += (v0.x + v1.x) + (v2.x + v3.x);
        acc.y += (v0.y + v1.y) + (v2.y + v3.y);
        acc.z += (v0.z + v1.z) + (v2.z + v3.z);
        acc.w += (v0.w + v1.w) + (v2.w + v3.w);
    }
    for (; e < end; ++e) {
        int s0 = __ldg(csrc + e);
        float4 v0 = __ldg(h4 + s0 * 32 + lane);
        acc.x += v0.x; acc.y += v0.y; acc.z += v0.z; acc.w += v0.w;
    }
    float iv = invd[node];
    float4 b = __ldg(h4 + node * 32 + lane);
    reinterpret_cast<float4*>(out)[node * 32 + lane] =
        make_float4(b.x + acc.x * iv, b.y + acc.y * iv,
                    b.z + acc.z * iv, b.w + acc.w * iv);
}

// ---------------- launch -----------------------------------------------------
extern "C" void kernel_launch(void* const* d_in, const int* in_sizes, int n_in,
                              void* d_out, int out_size)
{
    const float* x   = (const float*)d_in[0];
    const int*   src = (const int*)  d_in[1];
    const int*   dst = (const int*)  d_in[2];
    const float* W1  = (const float*)d_in[3];
    const float* b1  = (const float*)d_in[4];
    const float* W2  = (const float*)d_in[5];
    const float* b2  = (const float*)d_in[6];
    const float* W3  = (const float*)d_in[7];
    const float* b3  = (const float*)d_in[8];
    const float* Wo1 = (const float*)d_in[9];
    const float* bo1 = (const float*)d_in[10];
    const float* Wo2 = (const float*)d_in[11];
    const float* bo2 = (const float*)d_in[12];
    float* out = (float*)d_out;

    const int N = in_sizes[0] / FD;    // 100000
    const int E = in_sizes[1];         // 800000

    float *bufA, *bufB, *invd;
    int *deg, *off, *cnt, *bsum, *csrc;
    uint32_t* wpl;
    cudaGetSymbolAddress((void**)&bufA, g_bufA);
    cudaGetSymbolAddress((void**)&bufB, g_bufB);
    cudaGetSymbolAddress((void**)&invd, g_invdeg);
    cudaGetSymbolAddress((void**)&deg,  g_deg);
    cudaGetSymbolAddress((void**)&off,  g_off);
    cudaGetSymbolAddress((void**)&cnt,  g_cnt);
    cudaGetSymbolAddress((void**)&bsum, g_bsum);
    cudaGetSymbolAddress((void**)&csrc, g_csrc);
    cudaGetSymbolAddress((void**)&wpl,  g_wpl);

    // side stream + fork/join events (created once; capture-safe)
    static cudaStream_t sCSR = nullptr;
    static cudaEvent_t  evFork = nullptr, evJoin = nullptr;
    if (!sCSR) {
        cudaStreamCreateWithFlags(&sCSR, cudaStreamNonBlocking);
        cudaEventCreateWithFlags(&evFork, cudaEventDisableTiming);
        cudaEventCreateWithFlags(&evJoin, cudaEventDisableTiming);
    }

    cudaFuncSetAttribute(gemm_fusedN<2, false, 128, false>, cudaFuncAttributeMaxDynamicSharedMemorySize, SMEM_BYTES);
    cudaFuncSetAttribute(gemm_fusedN<3, false, 128, true >, cudaFuncAttributeMaxDynamicSharedMemorySize, SMEM_BYTES);
    cudaFuncSetAttribute(gemm_fusedN<3, true,  64,  false>, cudaFuncAttributeMaxDynamicSharedMemorySize, SMEM_BYTES);

    const int gb = (N + 63) / 64;                 // 1563 (64-row tiles)
    const int nb = (N + 1023) / 1024;             // 98 scan blocks
    const int ag = (N + 7) / 8;                   // aggregate: 8 warps/block

    const uint32_t* p0 = wpl;                     // W1
    const uint32_t* p1 = wpl + 1 * 2 * PW;        // W2
    const uint32_t* p2 = wpl + 2 * 2 * PW;        // W3
    const uint32_t* p3 = wpl + 3 * 2 * PW;        // Wo1
    const uint32_t* p4 = wpl + 4 * 2 * PW;        // Wo2

    // ---- fork: CSR build on side stream ----
    cudaEventRecord(evFork, 0);
    cudaStreamWaitEvent(sCSR, evFork, 0);

    zero_int_kernel<<<(N + 255) / 256, 256, 0, sCSR>>>(deg, N);
    hist_kernel<<<(E + 255) / 256, 256, 0, sCSR>>>(dst, E, deg);
    csr_scan1<<<nb, 1024, 0, sCSR>>>(deg, off, bsum, invd, cnt, N);
    csr_scan2<<<1, 128, 0, sCSR>>>(bsum, nb);
    csr_scan3<<<nb, 1024, 0, sCSR>>>(off, bsum, N);
    csr_fill<<<(E + 255) / 256, 256, 0, sCSR>>>(src, dst, off, cnt, csrc, E);
    cudaEventRecord(evJoin, sCSR);

    // ---- weight pre-split (once per call; tiny) ----
    wsplit_kernel<<<40, 256>>>(W1, W2, W3, Wo1, Wo2, wpl);

    // x2 = lin(relu(lin(x,W1,b1)),W2,b2)
    gemm_fusedN<2, false, 128, false><<<gb, 256, SMEM_BYTES>>>(
        x, p0, b1, p1, b2, nullptr, nullptr, bufA, N);

    // ---- join before first aggregate ----
    cudaStreamWaitEvent(0, evJoin, 0);

    // h = x2 + mean_agg(x2)
    aggregate_kernel<<<ag, 256>>>(bufA, off, csrc, invd, bufB, N);

    // h = relu(lin( lin(relu(lin(h,W1,b1)),W2,b2), W3,b3))
    gemm_fusedN<3, false, 128, true><<<gb, 256, SMEM_BYTES>>>(
        bufB, p0, b1, p1, b2, p2, b3, bufA, N);

    // h = h + mean_agg(h)
    aggregate_kernel<<<ag, 256>>>(bufA, off, csrc, invd, bufB, N);

    // out = lin( relu(lin( relu(lin(h,W3,b3)), Wo1,bo1)), Wo2,bo2)
    gemm_fusedN<3, true, 64, false><<<gb, 256, SMEM_BYTES>>>(
        bufB, p2, b3, p3, bo1, p4, bo2, out, N);
}